// round 14
// baseline (speedup 1.0000x reference)
#include <cuda_runtime.h>
#include <cstdint>

// Problem dims
#define T_DIM 32
#define B_DIM 64
#define D_DIM 256
#define P_DIM 1024
#define M_TOT (T_DIM * B_DIM)   // 2048
#define KNOTS 17

// Scratch (static device globals — no runtime allocation)
__device__ float g_x[M_TOT * P_DIM];     // 8 MB: raw proj@A (tf32 product)
__device__ float g_inv[P_DIM];           // 1/||A_col||
__device__ float g_partial[512];
__device__ int   g_count = 0;

// RNA(f32 -> tf32) == truncate(bits + 0x1000); the MMA input converter
// truncates, so one IADD on the bits gives exact round-to-nearest-away.
#define RNA_BIAS 0x1000u

typedef unsigned long long u64;
#define SGN_BOTH 0x8000000080000000ULL
#define SGN_HI   0x8000000000000000ULL
#define SGN_LO   0x0000000080000000ULL

#define FMA_F32X2(d, a, b, c) \
    asm("fma.rn.f32x2 %0, %1, %2, %3;" : "=l"(d) : "l"(a), "l"(b), "l"(c))
#define ADD_F32X2(d, a, b) \
    asm("add.rn.f32x2 %0, %1, %2;" : "=l"(d) : "l"(a), "l"(b))
#define PACK2(d, lo, hi) \
    asm("mov.b64 %0, {%1, %2};" : "=l"(d) : "r"(__float_as_uint(lo)), "r"(__float_as_uint(hi)))
#define UNPACK2(lo, hi, s) \
    do { unsigned _l, _h; \
         asm("mov.b64 {%0, %1}, %2;" : "=r"(_l), "=r"(_h) : "l"(s)); \
         lo = __uint_as_float(_l); hi = __uint_as_float(_h); } while (0)

// phi_k = exp(-(k*dt)^2/2), dt = 3/16
__device__ const float PHI_TAB[16] = {
    0.9825755f, 0.9321025f, 0.8536763f, 0.7548390f,
    0.6443885f, 0.5310960f, 0.4226005f, 0.3246525f,
    0.2407901f, 0.1724217f, 0.1191997f, 0.0795592f,
    0.0512672f, 0.0318948f, 0.0191572f, 0.0111090f
};

// ---------------------------------------------------------------------------
// Kernel 1: tf32 mma.sync GEMM (unchanged, proven).
// ---------------------------------------------------------------------------
#define ASTRIDE 68
#define BSTRIDE 136
#define CHUNKA_F (128 * ASTRIDE)
#define CHUNKB_F (64 * BSTRIDE)
#define NORM_OFF (2 * CHUNKA_F + 2 * CHUNKB_F)
#define GEMM_SMEM ((NORM_OFF + 128) * 4)

__device__ __forceinline__ void load_chunk(
    uint32_t sb, int buf, int kt, int m0, int n0,
    const float4* __restrict__ pa, const float4* __restrict__ pb, int tid)
{
    #pragma unroll
    for (int t = 0; t < 8; ++t) {
        int idx = t * 256 + tid;
        int row = idx >> 4;
        int c   = idx & 15;
        uint32_t off = (uint32_t)((buf * CHUNKA_F + row * ASTRIDE + c * 4) * 4);
        const float4* s = pa + (size_t)(m0 + row) * (D_DIM / 4) + kt * 16 + c;
        asm volatile("cp.async.cg.shared.global [%0], [%1], 16;"
                     :: "r"(sb + off), "l"(s));
    }
    #pragma unroll
    for (int t = 0; t < 8; ++t) {
        int idx = t * 256 + tid;
        int row = idx >> 5;
        int c   = idx & 31;
        uint32_t off = (uint32_t)((2 * CHUNKA_F + buf * CHUNKB_F
                                   + row * BSTRIDE + c * 4) * 4);
        const float4* s = pb + (size_t)(kt * 64 + row) * (P_DIM / 4) + n0 / 4 + c;
        asm volatile("cp.async.cg.shared.global [%0], [%1], 16;"
                     :: "r"(sb + off), "l"(s));
    }
}

__global__ __launch_bounds__(256, 1) void gemm_tc(
    const float* __restrict__ pA, const float* __restrict__ pB)
{
    extern __shared__ float sm[];
    uint32_t sb;
    asm("{ .reg .u64 t; cvta.to.shared.u64 t, %1; cvt.u32.u64 %0, t; }"
        : "=r"(sb) : "l"(sm));

    const int tid = threadIdx.x;
    const int wid = tid >> 5;
    const int lid = tid & 31;
    const int gid = lid >> 2;
    const int tig = lid & 3;
    const int wm  = (wid >> 2) * 64;
    const int wn  = (wid & 3) * 32;
    const int m0  = blockIdx.y * 128;
    const int n0  = blockIdx.x * 128;
    const bool do_norm = (blockIdx.y == 0);
    const int ncol = tid & 127;
    const int nhalf = tid >> 7;

    const float4* pa = (const float4*)pA;
    const float4* pb = (const float4*)pB;

    float acc[4][4][4];
    #pragma unroll
    for (int mi = 0; mi < 4; ++mi)
        #pragma unroll
        for (int ni = 0; ni < 4; ++ni)
            #pragma unroll
            for (int r = 0; r < 4; ++r) acc[mi][ni][r] = 0.f;
    float nsq = 0.f;

    load_chunk(sb, 0, 0, m0, n0, pa, pb, tid);
    asm volatile("cp.async.commit_group;" ::: "memory");

    #pragma unroll
    for (int kt = 0; kt < 4; ++kt) {
        if (kt < 3) {
            load_chunk(sb, (kt + 1) & 1, kt + 1, m0, n0, pa, pb, tid);
            asm volatile("cp.async.commit_group;" ::: "memory");
            asm volatile("cp.async.wait_group 1;" ::: "memory");
        } else {
            asm volatile("cp.async.wait_group 0;" ::: "memory");
        }
        __syncthreads();

        const int buf = kt & 1;
        const float* As = sm + buf * CHUNKA_F;
        const float* Bs = sm + 2 * CHUNKA_F + buf * CHUNKB_F;

        if (do_norm) {
            const float* np = Bs + nhalf * 32 * BSTRIDE + ncol;
            #pragma unroll
            for (int j = 0; j < 32; ++j) {
                float v = np[j * BSTRIDE];
                nsq += v * v;
            }
        }

        #pragma unroll
        for (int ks = 0; ks < 8; ++ks) {
            const int kc = ks * 8;
            uint32_t a[4][4];
            #pragma unroll
            for (int mi = 0; mi < 4; ++mi) {
                const float* ap = As + (wm + mi * 16 + gid) * ASTRIDE + kc + tig;
                a[mi][0] = __float_as_uint(ap[0])               + RNA_BIAS;
                a[mi][1] = __float_as_uint(ap[8 * ASTRIDE])     + RNA_BIAS;
                a[mi][2] = __float_as_uint(ap[4])               + RNA_BIAS;
                a[mi][3] = __float_as_uint(ap[8 * ASTRIDE + 4]) + RNA_BIAS;
            }
            uint32_t b[4][2];
            #pragma unroll
            for (int ni = 0; ni < 4; ++ni) {
                const float* bp = Bs + (kc + tig) * BSTRIDE + wn + ni * 8 + gid;
                b[ni][0] = __float_as_uint(bp[0])               + RNA_BIAS;
                b[ni][1] = __float_as_uint(bp[4 * BSTRIDE])     + RNA_BIAS;
            }
            #pragma unroll
            for (int mi = 0; mi < 4; ++mi)
                #pragma unroll
                for (int ni = 0; ni < 4; ++ni)
                    asm volatile(
                        "mma.sync.aligned.m16n8k8.row.col.f32.tf32.tf32.f32 "
                        "{%0,%1,%2,%3}, {%4,%5,%6,%7}, {%8,%9}, {%0,%1,%2,%3};"
                        : "+f"(acc[mi][ni][0]), "+f"(acc[mi][ni][1]),
                          "+f"(acc[mi][ni][2]), "+f"(acc[mi][ni][3])
                        : "r"(a[mi][0]), "r"(a[mi][1]), "r"(a[mi][2]), "r"(a[mi][3]),
                          "r"(b[ni][0]), "r"(b[ni][1]));
        }
        __syncthreads();
    }

    if (do_norm) {
        if (nhalf == 1) sm[NORM_OFF + ncol] = nsq;
        __syncthreads();
        if (nhalf == 0) {
            float t = nsq + sm[NORM_OFF + ncol];
            g_inv[n0 + ncol] = 1.f / fmaxf(sqrtf(t), 1e-12f);
        }
    }

    #pragma unroll
    for (int mi = 0; mi < 4; ++mi) {
        const int m = m0 + wm + mi * 16 + gid;
        #pragma unroll
        for (int ni = 0; ni < 4; ++ni) {
            const int n = n0 + wn + ni * 8 + tig * 2;
            float2 v0 = { acc[mi][ni][0], acc[mi][ni][1] };
            float2 v1 = { acc[mi][ni][2], acc[mi][ni][3] };
            *(float2*)&g_x[(size_t)m * P_DIM + n]       = v0;
            *(float2*)&g_x[(size_t)(m + 8) * P_DIM + n] = v1;
        }
    }
}

// ---------------------------------------------------------------------------
// Kernel 2: trig.  512 blocks (16 p-blocks x 32 t), 512 threads =
// 2 knot-parities x 4 b-quarters x 64 p.  SMEM-staged x tile; per-(b,thread):
// one sincos + one double-angle seed, then an 8-STEP dual-carry packed
// Chebyshev chain over this thread's knot parity:
//   cos((k+2)a) = 2cos(2a)cos(ka) - cos((k-2)a)
// step = 2 packed FMA + 1 packed ADD (fma pipe only).  ~40 regs ->
// 3 blocks/SM (48 warps, 75% occ).  Fused deterministic final reduction.
// ---------------------------------------------------------------------------
#define MERGE2_F (3 * 2 * 8 * 64 * 2)        // 6144 floats
#define TRIG_SMEM ((MERGE2_F + 512) * 4)     // 26624 B

__global__ __launch_bounds__(512, 3) void trig_kernel(float* __restrict__ out)
{
    extern __shared__ float ts[];
    float* xs  = ts;                 // phase 1: [64 b][64 p] tile (16 KB)
    float* mrg = ts;                 // phase 2: [3 bq][2 par][8 i][64 p][2]
    float* red = ts + MERGE2_F;      // [512]

    const int t   = blockIdx.y;
    const int pl  = threadIdx.x & 63;
    const int sub = threadIdx.x >> 6;     // 0..7
    const int par = sub & 1;              // 0: odd knots, 1: even knots
    const int bq  = sub >> 1;             // 0..3: b quarter
    const int p   = blockIdx.x * 64 + pl;
    const float dt = 3.0f / 16.0f;
    const float sc = dt * g_inv[p];

    // Stage x tile: 64 b-rows x 64 p = 1024 float4, 2 per thread
    {
        uint32_t sb;
        asm("{ .reg .u64 a; cvta.to.shared.u64 a, %1; cvt.u32.u64 %0, a; }"
            : "=r"(sb) : "l"(ts));
        const float4* gx = (const float4*)(g_x + (size_t)(t * B_DIM) * P_DIM
                                           + blockIdx.x * 64);
        #pragma unroll
        for (int i = 0; i < 2; ++i) {
            int idx = i * 512 + threadIdx.x;    // 0..1023
            int row = idx >> 4;                 // 0..63
            int c   = idx & 15;                 // 0..15
            uint32_t dst = sb + (uint32_t)(row * 256 + c * 16);
            const float4* src = gx + (size_t)row * (P_DIM / 4) + c;
            asm volatile("cp.async.cg.shared.global [%0], [%1], 16;"
                         :: "r"(dst), "l"(src));
        }
        asm volatile("cp.async.commit_group;" ::: "memory");
        asm volatile("cp.async.wait_group 0;" ::: "memory");
    }
    __syncthreads();

    u64 acc[8];                      // packed (cos,sin) sums for 8 knots
    #pragma unroll
    for (int i = 0; i < 8; ++i) acc[i] = 0ull;

    const float* xrow = xs + bq * 16 * 64 + pl;
    for (int b = 0; b < 16; ++b) {
        float x = xrow[b * 64];
        float s1, c1;
        __sincosf(x * sc, &s1, &c1);
        float c2 = fmaf(2.f * c1, c1, -1.f);      // cos(2a)
        float s2 = 2.f * s1 * c1;                 // sin(2a)
        u64 tc2, ntc2, cur, curm, prev, prevm;
        {
            float tc = 2.f * c2;
            PACK2(tc2, tc, tc);
            ntc2 = tc2 ^ SGN_BOTH;
        }
        if (par == 0) {               // odd knots 1,3,...,15; prev = k=-1
            PACK2(cur, c1, s1);
            curm  = cur ^ SGN_BOTH;
            prev  = cur ^ SGN_HI;     // ( c1, -s1)
            prevm = cur ^ SGN_LO;     // (-c1,  s1)
        } else {                      // even knots 2,4,...,16; prev = k=0
            PACK2(cur, c2, s2);
            curm  = cur ^ SGN_BOTH;
            PACK2(prev, 1.f, 0.f);
            PACK2(prevm, -1.f, 0.f);
        }
        #pragma unroll
        for (int i = 0; i < 8; ++i) {
            ADD_F32X2(acc[i], acc[i], cur);
            u64 nxt, nxtm;
            FMA_F32X2(nxt,  tc2,  cur, prevm);    // next   =  tc*cur - prev
            FMA_F32X2(nxtm, ntc2, cur, prev);     // -(next)
            prev = cur; prevm = curm;
            cur = nxt;  curm = nxtm;
        }
    }

    __syncthreads();   // all xs reads complete before merge overwrites it

    // Merge b-quarters 1..3 into quarter 0 (per parity; knots disjoint)
    if (bq > 0) {
        float* mb = mrg + ((bq - 1) * 2 + par) * 8 * 64 * 2;
        #pragma unroll
        for (int i = 0; i < 8; ++i) {
            float cv, sv;
            UNPACK2(cv, sv, acc[i]);
            mb[(i * 64 + pl) * 2 + 0] = cv;
            mb[(i * 64 + pl) * 2 + 1] = sv;
        }
    }
    __syncthreads();

    float val = 0.f;
    if (bq == 0) {
        const float invB = 1.f / (float)B_DIM;
        #pragma unroll
        for (int i = 0; i < 8; ++i) {
            int k = par ? (2 * i + 2) : (2 * i + 1);
            float cs, ss;
            UNPACK2(cs, ss, acc[i]);
            #pragma unroll
            for (int sgm = 0; sgm < 3; ++sgm) {
                const float* mb = mrg + (sgm * 2 + par) * 8 * 64 * 2;
                cs += mb[(i * 64 + pl) * 2 + 0];
                ss += mb[(i * 64 + pl) * 2 + 1];
            }
            float phik = PHI_TAB[k - 1];
            float wk   = ((k == 16) ? dt : 2.f * dt) * phik;
            float cm = cs * invB - phik;
            float smn = ss * invB;
            val += wk * (cm * cm + smn * smn);
        }
        val *= (float)B_DIM;
    }

    red[threadIdx.x] = val;
    __syncthreads();
    #pragma unroll
    for (int s = 256; s > 0; s >>= 1) {
        if (threadIdx.x < s) red[threadIdx.x] += red[threadIdx.x + s];
        __syncthreads();
    }

    __shared__ int is_last;
    if (threadIdx.x == 0) {
        g_partial[blockIdx.y * gridDim.x + blockIdx.x] = red[0];
        __threadfence();
        int prev = atomicAdd(&g_count, 1);
        is_last = (prev == (int)(gridDim.x * gridDim.y) - 1);
    }
    __syncthreads();

    if (is_last) {
        red[threadIdx.x] = g_partial[threadIdx.x];
        __syncthreads();
        #pragma unroll
        for (int s = 256; s > 0; s >>= 1) {
            if (threadIdx.x < s) red[threadIdx.x] += red[threadIdx.x + s];
            __syncthreads();
        }
        if (threadIdx.x == 0) {
            out[0] = red[0] * (1.0f / (float)(T_DIM * P_DIM));
            g_count = 0;   // reset so graph replays are deterministic
        }
    }
}

// ---------------------------------------------------------------------------
extern "C" void kernel_launch(void* const* d_in, const int* in_sizes, int n_in,
                              void* d_out, int out_size)
{
    const float* proj = (const float*)d_in[0];   // (32,64,256)
    const float* Amat = (const float*)d_in[1];   // (256,1024)
    float* out = (float*)d_out;

    cudaFuncSetAttribute(gemm_tc, cudaFuncAttributeMaxDynamicSharedMemorySize,
                         GEMM_SMEM);
    cudaFuncSetAttribute(trig_kernel, cudaFuncAttributeMaxDynamicSharedMemorySize,
                         TRIG_SMEM);

    dim3 g1(P_DIM / 128, M_TOT / 128);   // (8, 16)
    gemm_tc<<<g1, 256, GEMM_SMEM>>>(proj, Amat);

    dim3 g2(P_DIM / 64, T_DIM);          // (16, 32) -> 512 blocks
    trig_kernel<<<g2, 512, TRIG_SMEM>>>(out);
}

// round 15
// speedup vs baseline: 1.1764x; 1.1764x over previous
#include <cuda_runtime.h>
#include <cstdint>

// Problem dims
#define T_DIM 32
#define B_DIM 64
#define D_DIM 256
#define P_DIM 1024
#define M_TOT (T_DIM * B_DIM)   // 2048
#define KNOTS 17

// Scratch (static device globals — no runtime allocation)
__device__ float g_partial[128];
__device__ int   g_count = 0;

// RNA(f32 -> tf32) == truncate(bits + 0x1000)
#define RNA_BIAS 0x1000u

typedef unsigned long long u64;
#define SGN_BOTH 0x8000000080000000ULL

#define FMA_F32X2(d, a, b, c) \
    asm("fma.rn.f32x2 %0, %1, %2, %3;" : "=l"(d) : "l"(a), "l"(b), "l"(c))
#define ADD_F32X2(d, a, b) \
    asm("add.rn.f32x2 %0, %1, %2;" : "=l"(d) : "l"(a), "l"(b))
#define PACK2(d, lo, hi) \
    asm("mov.b64 %0, {%1, %2};" : "=l"(d) : "r"(__float_as_uint(lo)), "r"(__float_as_uint(hi)))
#define UNPACK2(lo, hi, s) \
    do { unsigned _l, _h; \
         asm("mov.b64 {%0, %1}, %2;" : "=r"(_l), "=r"(_h) : "l"(s)); \
         lo = __uint_as_float(_l); hi = __uint_as_float(_h); } while (0)

// phi_k = exp(-(k*dt)^2/2), dt = 3/16
__device__ const float PHI_TAB[16] = {
    0.9825755f, 0.9321025f, 0.8536763f, 0.7548390f,
    0.6443885f, 0.5310960f, 0.4226005f, 0.3246525f,
    0.2407901f, 0.1724217f, 0.1191997f, 0.0795592f,
    0.0512672f, 0.0318948f, 0.0191572f, 0.0111090f
};

// ---------------------------------------------------------------------------
// Single fused kernel: tf32 GEMM (proven mainloop) + in-block column norms +
// epilogue trig statistic.  M-tile 128 = 2 t-groups x full 64-b range, so the
// entire per-(t,p) characteristic-function reduction happens in-block with
// NO global x traffic.  Fused deterministic final reduction via counter.
// ---------------------------------------------------------------------------
#define ASTRIDE 68
#define BSTRIDE 136
#define CHUNKA_F (128 * ASTRIDE)
#define CHUNKB_F (64 * BSTRIDE)
#define GEMM_SMEM ((2 * CHUNKA_F + 2 * CHUNKB_F + 128) * 4)   // 139776 B

// Epilogue SMEM layout (reuses chunk region after mainloop):
#define XT_STRIDE 132
#define XT_F      (128 * XT_STRIDE)          // 16896 floats (67.6 KB)
#define INV_OFF   XT_F                       // [128] inv norms
#define NSCR_OFF  (XT_F + 128)               // [128] norm scratch
#define RED_OFF   (XT_F + 256)               // [256] reduction

__device__ __forceinline__ void load_chunk(
    uint32_t sb, int buf, int kt, int m0, int n0,
    const float4* __restrict__ pa, const float4* __restrict__ pb, int tid)
{
    #pragma unroll
    for (int t = 0; t < 8; ++t) {
        int idx = t * 256 + tid;
        int row = idx >> 4;
        int c   = idx & 15;
        uint32_t off = (uint32_t)((buf * CHUNKA_F + row * ASTRIDE + c * 4) * 4);
        const float4* s = pa + (size_t)(m0 + row) * (D_DIM / 4) + kt * 16 + c;
        asm volatile("cp.async.cg.shared.global [%0], [%1], 16;"
                     :: "r"(sb + off), "l"(s));
    }
    #pragma unroll
    for (int t = 0; t < 8; ++t) {
        int idx = t * 256 + tid;
        int row = idx >> 5;
        int c   = idx & 31;
        uint32_t off = (uint32_t)((2 * CHUNKA_F + buf * CHUNKB_F
                                   + row * BSTRIDE + c * 4) * 4);
        const float4* s = pb + (size_t)(kt * 64 + row) * (P_DIM / 4) + n0 / 4 + c;
        asm volatile("cp.async.cg.shared.global [%0], [%1], 16;"
                     :: "r"(sb + off), "l"(s));
    }
}

__global__ __launch_bounds__(256, 1) void fused_kernel(
    const float* __restrict__ pA, const float* __restrict__ pB,
    float* __restrict__ out)
{
    extern __shared__ float sm[];
    uint32_t sb;
    asm("{ .reg .u64 t; cvta.to.shared.u64 t, %1; cvt.u32.u64 %0, t; }"
        : "=r"(sb) : "l"(sm));

    const int tid = threadIdx.x;
    const int wid = tid >> 5;
    const int lid = tid & 31;
    const int gid = lid >> 2;
    const int tig = lid & 3;
    const int wm  = (wid >> 2) * 64;
    const int wn  = (wid & 3) * 32;
    const int m0  = blockIdx.y * 128;
    const int n0  = blockIdx.x * 128;
    const int ncol = tid & 127;
    const int nhalf = tid >> 7;

    const float4* pa = (const float4*)pA;
    const float4* pb = (const float4*)pB;

    float acc[4][4][4];
    #pragma unroll
    for (int mi = 0; mi < 4; ++mi)
        #pragma unroll
        for (int ni = 0; ni < 4; ++ni)
            #pragma unroll
            for (int r = 0; r < 4; ++r) acc[mi][ni][r] = 0.f;
    float nsq = 0.f;

    load_chunk(sb, 0, 0, m0, n0, pa, pb, tid);
    asm volatile("cp.async.commit_group;" ::: "memory");

    #pragma unroll
    for (int kt = 0; kt < 4; ++kt) {
        if (kt < 3) {
            load_chunk(sb, (kt + 1) & 1, kt + 1, m0, n0, pa, pb, tid);
            asm volatile("cp.async.commit_group;" ::: "memory");
            asm volatile("cp.async.wait_group 1;" ::: "memory");
        } else {
            asm volatile("cp.async.wait_group 0;" ::: "memory");
        }
        __syncthreads();

        const int buf = kt & 1;
        const float* As = sm + buf * CHUNKA_F;
        const float* Bs = sm + 2 * CHUNKA_F + buf * CHUNKB_F;

        // Column sum-of-squares (all blocks: B panel covers all 256 k rows)
        {
            const float* np = Bs + nhalf * 32 * BSTRIDE + ncol;
            #pragma unroll
            for (int j = 0; j < 32; ++j) {
                float v = np[j * BSTRIDE];
                nsq += v * v;
            }
        }

        #pragma unroll
        for (int ks = 0; ks < 8; ++ks) {
            const int kc = ks * 8;
            uint32_t a[4][4];
            #pragma unroll
            for (int mi = 0; mi < 4; ++mi) {
                const float* ap = As + (wm + mi * 16 + gid) * ASTRIDE + kc + tig;
                a[mi][0] = __float_as_uint(ap[0])               + RNA_BIAS;
                a[mi][1] = __float_as_uint(ap[8 * ASTRIDE])     + RNA_BIAS;
                a[mi][2] = __float_as_uint(ap[4])               + RNA_BIAS;
                a[mi][3] = __float_as_uint(ap[8 * ASTRIDE + 4]) + RNA_BIAS;
            }
            uint32_t b[4][2];
            #pragma unroll
            for (int ni = 0; ni < 4; ++ni) {
                const float* bp = Bs + (kc + tig) * BSTRIDE + wn + ni * 8 + gid;
                b[ni][0] = __float_as_uint(bp[0])               + RNA_BIAS;
                b[ni][1] = __float_as_uint(bp[4 * BSTRIDE])     + RNA_BIAS;
            }
            #pragma unroll
            for (int mi = 0; mi < 4; ++mi)
                #pragma unroll
                for (int ni = 0; ni < 4; ++ni)
                    asm volatile(
                        "mma.sync.aligned.m16n8k8.row.col.f32.tf32.tf32.f32 "
                        "{%0,%1,%2,%3}, {%4,%5,%6,%7}, {%8,%9}, {%0,%1,%2,%3};"
                        : "+f"(acc[mi][ni][0]), "+f"(acc[mi][ni][1]),
                          "+f"(acc[mi][ni][2]), "+f"(acc[mi][ni][3])
                        : "r"(a[mi][0]), "r"(a[mi][1]), "r"(a[mi][2]), "r"(a[mi][3]),
                          "r"(b[ni][0]), "r"(b[ni][1]));
        }
        __syncthreads();
    }

    // ---- Norm combine (SMEM scratch beyond the x-tile region) ----
    if (nhalf == 1) sm[NSCR_OFF + ncol] = nsq;
    __syncthreads();
    if (nhalf == 0) {
        float tot = nsq + sm[NSCR_OFF + ncol];
        sm[INV_OFF + ncol] = 1.f / fmaxf(sqrtf(tot), 1e-12f);
    }

    // ---- Phase A: spill acc fragments to SMEM x-tile [m][n], stride 132 ----
    #pragma unroll
    for (int mi = 0; mi < 4; ++mi) {
        const int m = wm + mi * 16 + gid;
        #pragma unroll
        for (int ni = 0; ni < 4; ++ni) {
            const int n = wn + ni * 8 + tig * 2;
            float2 v0 = { acc[mi][ni][0], acc[mi][ni][1] };
            float2 v1 = { acc[mi][ni][2], acc[mi][ni][3] };
            *(float2*)&sm[m * XT_STRIDE + n]       = v0;
            *(float2*)&sm[(m + 8) * XT_STRIDE + n] = v1;
        }
    }
    __syncthreads();

    // ---- Phase B: one thread per (t-group, col): 64-b packed Chebyshev ----
    const int tg  = tid >> 7;            // 0/1
    const int col = tid & 127;
    const float dt = 3.0f / 16.0f;
    const float sc = dt * sm[INV_OFF + col];

    u64 kacc[KNOTS - 1];
    #pragma unroll
    for (int k = 0; k < KNOTS - 1; ++k) kacc[k] = 0ull;

    const float* xrow = sm + tg * 64 * XT_STRIDE + col;
    #pragma unroll 2
    for (int b = 0; b < 64; ++b) {
        float x = xrow[b * XT_STRIDE];
        float s1, c1;
        __sincosf(x * sc, &s1, &c1);
        const float tc = 2.f * c1;
        u64 cur, prev, tc2;
        PACK2(cur, c1, s1);
        PACK2(prev, 1.f, 0.f);
        PACK2(tc2, tc, tc);
        #pragma unroll
        for (int k = 0; k < KNOTS - 1; ++k) {
            ADD_F32X2(kacc[k], kacc[k], cur);
            u64 np = prev ^ SGN_BOTH;
            u64 nxt;
            FMA_F32X2(nxt, tc2, cur, np);
            prev = cur; cur = nxt;
        }
    }

    float val = 0.f;
    {
        const float invB = 1.f / (float)B_DIM;
        #pragma unroll
        for (int k = 1; k <= 16; ++k) {
            float phik = PHI_TAB[k - 1];
            float wk   = ((k == 16) ? dt : 2.f * dt) * phik;
            float cs, ss;
            UNPACK2(cs, ss, kacc[k - 1]);
            float cm = cs * invB - phik;
            float smn = ss * invB;
            val += wk * (cm * cm + smn * smn);
        }
        val *= (float)B_DIM;
    }

    // ---- Block reduction + fused deterministic final reduction ----
    __syncthreads();   // xs reads done before red (shares SMEM budget anyway)
    float* red = sm + RED_OFF;
    red[tid] = val;
    __syncthreads();
    #pragma unroll
    for (int s = 128; s > 0; s >>= 1) {
        if (tid < s) red[tid] += red[tid + s];
        __syncthreads();
    }

    __shared__ int is_last;
    if (tid == 0) {
        g_partial[blockIdx.y * gridDim.x + blockIdx.x] = red[0];
        __threadfence();
        int prev = atomicAdd(&g_count, 1);
        is_last = (prev == (int)(gridDim.x * gridDim.y) - 1);
    }
    __syncthreads();

    if (is_last) {
        red[tid] = (tid < 128) ? g_partial[tid] : 0.f;
        __syncthreads();
        #pragma unroll
        for (int s = 128; s > 0; s >>= 1) {
            if (tid < s) red[tid] += red[tid + s];
            __syncthreads();
        }
        if (tid == 0) {
            out[0] = red[0] * (1.0f / (float)(T_DIM * P_DIM));
            g_count = 0;   // reset so graph replays are deterministic
        }
    }
}

// ---------------------------------------------------------------------------
extern "C" void kernel_launch(void* const* d_in, const int* in_sizes, int n_in,
                              void* d_out, int out_size)
{
    const float* proj = (const float*)d_in[0];   // (32,64,256)
    const float* Amat = (const float*)d_in[1];   // (256,1024)
    float* out = (float*)d_out;

    cudaFuncSetAttribute(fused_kernel, cudaFuncAttributeMaxDynamicSharedMemorySize,
                         GEMM_SMEM);

    dim3 g1(P_DIM / 128, M_TOT / 128);   // (8, 16) = 128 blocks
    fused_kernel<<<g1, 256, GEMM_SMEM>>>(proj, Amat, out);
}